// round 1
// baseline (speedup 1.0000x reference)
#include <cuda_runtime.h>

// ConjunctionLayer: out[b,j] = -1/(-1 + sum_i log(1 - (1-x[b,i]) * W[j,i]))
// B=4096, D=512, N=128, fp32.
//
// Strategy: sum(log Z) == log(prod Z). Z in (0.5, 1], so a product over 64
// elements stays >= 0.5^64 ~ 5.4e-20 (normal fp32). Accumulate FMUL products,
// one MUFU.LG2 per 64 elements -> pure FMA-pipe kernel.

#define Bdim 4096
#define Ddim 512
#define Ndim 128

#define TB 32      // b-rows per CTA
#define KC 64      // k-chunk (also the log-flush group: 0.5^64 is safe)
#define PX 33      // sx row pad (conflict-free transpose stores)
#define PW 132     // sw row pad (mult of 4 -> LDS.128 aligned; stores 8-way, cheap)

__global__ __launch_bounds__(256, 2)
void conj_kernel(const float* __restrict__ x,
                 const float* __restrict__ W,
                 float* __restrict__ out) {
    __shared__ float sx[KC][PX];   // a = x - 1, k-major
    __shared__ float sw[KC][PW];   // W, k-major

    const int tid   = threadIdx.x;
    const int b_blk = blockIdx.x * TB;
    const int tj    = tid & 15;    // 16 threads along j
    const int tb    = tid >> 4;    // 16 threads along b
    const int j0    = tj * 8;      // RJ = 8
    const int b0    = tb * 2;      // RB = 2

    float prod[2][8];
    float lsum[2][8];
#pragma unroll
    for (int r = 0; r < 2; r++)
#pragma unroll
        for (int c = 0; c < 8; c++) { prod[r][c] = 1.0f; lsum[r][c] = 0.0f; }

    for (int k0 = 0; k0 < Ddim; k0 += KC) {
        // stage x chunk (TB x KC = 2048 elems, 8/thread), transposed, a = x-1
#pragma unroll
        for (int t = 0; t < (TB * KC) / 256; t++) {
            int idx = tid + t * 256;
            int b = idx >> 6;        // idx / KC
            int k = idx & (KC - 1);
            sx[k][b] = x[(b_blk + b) * Ddim + k0 + k] - 1.0f;
        }
        // stage W chunk (Ndim x KC = 8192 elems, 32/thread), transposed
#pragma unroll
        for (int t = 0; t < (Ndim * KC) / 256; t++) {
            int idx = tid + t * 256;
            int j = idx >> 6;
            int k = idx & (KC - 1);
            sw[k][j] = W[j * Ddim + k0 + k];
        }
        __syncthreads();

#pragma unroll 8
        for (int i = 0; i < KC; i++) {
            float a0 = sx[i][b0];
            float a1 = sx[i][b0 + 1];
            float4 w0 = *(const float4*)&sw[i][j0];
            float4 w1 = *(const float4*)&sw[i][j0 + 4];
            float wv[8] = { w0.x, w0.y, w0.z, w0.w, w1.x, w1.y, w1.z, w1.w };
#pragma unroll
            for (int c = 0; c < 8; c++) {
                prod[0][c] *= fmaf(a0, wv[c], 1.0f);
                prod[1][c] *= fmaf(a1, wv[c], 1.0f);
            }
        }
        __syncthreads();

        // flush products into log2-sums (1 MUFU per 64 elements)
#pragma unroll
        for (int r = 0; r < 2; r++)
#pragma unroll
            for (int c = 0; c < 8; c++) {
                lsum[r][c] += __log2f(prod[r][c]);
                prod[r][c] = 1.0f;
            }
    }

    const float LN2 = 0.6931471805599453f;
#pragma unroll
    for (int r = 0; r < 2; r++) {
        int b = b_blk + b0 + r;
        float v[8];
#pragma unroll
        for (int c = 0; c < 8; c++) {
            float s = lsum[r][c] * LN2;
            v[c] = -1.0f / (-1.0f + s);
        }
        float4 o0 = make_float4(v[0], v[1], v[2], v[3]);
        float4 o1 = make_float4(v[4], v[5], v[6], v[7]);
        *(float4*)&out[b * Ndim + j0]     = o0;
        *(float4*)&out[b * Ndim + j0 + 4] = o1;
    }
}

extern "C" void kernel_launch(void* const* d_in, const int* in_sizes, int n_in,
                              void* d_out, int out_size) {
    const float* x = (const float*)d_in[0];   // (4096, 512)
    const float* W = (const float*)d_in[1];   // (128, 512)
    float* out = (float*)d_out;               // (4096, 128)
    (void)in_sizes; (void)n_in; (void)out_size;

    dim3 grid(Bdim / TB);   // 128 CTAs
    dim3 block(256);
    conj_kernel<<<grid, block>>>(x, W, out);
}

// round 2
// speedup vs baseline: 1.5409x; 1.5409x over previous
#include <cuda_runtime.h>

// ConjunctionLayer: out[b,j] = -1/(-1 + sum_k log(1 - (1-x[b,k]) * W[j,k]))
// B=4096, D=512, N=128, fp32.
//
// sum(log Z) == log(prod Z), Z in (0.5, 1], so products of 64 Z's stay >= 0.5^64
// (normal fp32). Packed f32x2 math: even-k in lo lane, odd-k in hi lane of each
// packed product; merged (lo*hi) at each flush. k-major smem, no transposes.

#define Bdim 4096
#define Ddim 512
#define Ndim 128

#define TB   16    // b-rows per CTA -> 256 CTAs
#define KC   64    // k-chunk (flush group)
#define SSTR 68    // smem row stride in words (16B aligned, bank-staggered)

typedef unsigned long long ull;

__device__ __forceinline__ ull fma2(ull a, ull b, ull c) {
    ull d;
    asm("fma.rn.f32x2 %0, %1, %2, %3;" : "=l"(d) : "l"(a), "l"(b), "l"(c));
    return d;
}
__device__ __forceinline__ ull mul2(ull a, ull b) {
    ull d;
    asm("mul.rn.f32x2 %0, %1, %2;" : "=l"(d) : "l"(a), "l"(b));
    return d;
}
__device__ __forceinline__ void unpack2(ull v, float& lo, float& hi) {
    asm("mov.b64 {%0, %1}, %2;" : "=f"(lo), "=f"(hi) : "l"(v));
}

__global__ __launch_bounds__(256, 2)
void conj_kernel(const float* __restrict__ x,
                 const float* __restrict__ W,
                 float* __restrict__ out) {
    __shared__ float sx[TB * SSTR];     // (x - 1), k-contiguous rows
    __shared__ float sw[Ndim * SSTR];   // W, k-contiguous rows

    const int tid   = threadIdx.x;
    const int b_blk = blockIdx.x * TB;
    const int tj    = tid >> 4;         // 0..15 -> phase-broadcast W reads
    const int tb    = tid & 15;         // 0..15 -> b row
    const int j0    = tj * 8;

    const ull ONE2 = 0x3F8000003F800000ull;  // {1.0f, 1.0f}

    ull   prod[8];
    float lsum[8];
#pragma unroll
    for (int c = 0; c < 8; c++) { prod[c] = ONE2; lsum[c] = 0.0f; }

    // staging map (float4 granularity, verbatim k-major copies)
    const int xr  = tid >> 4;           // x: row 0..15, 16 float4 per row
    const int xc4 = tid & 15;

    // ---- prefetch chunk 0 into registers ----
    float4 px;
    float4 pw[8];
    {
        float4 v = *(const float4*)&x[(b_blk + xr) * Ddim + xc4 * 4];
        px = make_float4(v.x - 1.0f, v.y - 1.0f, v.z - 1.0f, v.w - 1.0f);
#pragma unroll
        for (int t = 0; t < 8; t++) {
            int idx4 = tid + t * 256;
            int r  = idx4 >> 4;
            int c4 = idx4 & 15;
            pw[t] = *(const float4*)&W[r * Ddim + c4 * 4];
        }
    }

    for (int ch = 0; ch < Ddim / KC; ch++) {
        // ---- store prefetched chunk into smem ----
        *(float4*)&sx[xr * SSTR + xc4 * 4] = px;
#pragma unroll
        for (int t = 0; t < 8; t++) {
            int idx4 = tid + t * 256;
            int r  = idx4 >> 4;
            int c4 = idx4 & 15;
            *(float4*)&sw[r * SSTR + c4 * 4] = pw[t];
        }
        __syncthreads();

        // ---- prefetch next chunk ----
        if (ch + 1 < Ddim / KC) {
            int k0n = (ch + 1) * KC;
            float4 v = *(const float4*)&x[(b_blk + xr) * Ddim + k0n + xc4 * 4];
            px = make_float4(v.x - 1.0f, v.y - 1.0f, v.z - 1.0f, v.w - 1.0f);
#pragma unroll
            for (int t = 0; t < 8; t++) {
                int idx4 = tid + t * 256;
                int r  = idx4 >> 4;
                int c4 = idx4 & 15;
                pw[t] = *(const float4*)&W[r * Ddim + k0n + c4 * 4];
            }
        }

        // ---- compute: 4 k's per step, 8 j's per thread ----
#pragma unroll
        for (int kk = 0; kk < KC; kk += 4) {
            longlong2 av = *(const longlong2*)&sx[tb * SSTR + kk];  // {a_k,a_k+1},{a_k+2,a_k+3}
#pragma unroll
            for (int c = 0; c < 8; c++) {
                longlong2 wv = *(const longlong2*)&sw[(j0 + c) * SSTR + kk];
                prod[c] = mul2(prod[c], fma2((ull)av.x, (ull)wv.x, ONE2));
                prod[c] = mul2(prod[c], fma2((ull)av.y, (ull)wv.y, ONE2));
            }
        }
        __syncthreads();

        // ---- flush: one log2 per 64 elements per (b,j) ----
#pragma unroll
        for (int c = 0; c < 8; c++) {
            float lo, hi;
            unpack2(prod[c], lo, hi);
            lsum[c] += __log2f(lo * hi);
            prod[c] = ONE2;
        }
    }

    // ---- epilogue: y = -1 / (-1 + ln2 * lsum) ----
    const float LN2 = 0.6931471805599453f;
    float v[8];
#pragma unroll
    for (int c = 0; c < 8; c++) {
        float s = lsum[c] * LN2;
        v[c] = __fdividef(-1.0f, s - 1.0f);
    }
    float* orow = &out[(b_blk + tb) * Ndim + j0];
    *(float4*)&orow[0] = make_float4(v[0], v[1], v[2], v[3]);
    *(float4*)&orow[4] = make_float4(v[4], v[5], v[6], v[7]);
}

extern "C" void kernel_launch(void* const* d_in, const int* in_sizes, int n_in,
                              void* d_out, int out_size) {
    const float* x = (const float*)d_in[0];   // (4096, 512)
    const float* W = (const float*)d_in[1];   // (128, 512)
    float* out = (float*)d_out;               // (4096, 128)
    (void)in_sizes; (void)n_in; (void)out_size;

    dim3 grid(Bdim / TB);   // 256 CTAs
    dim3 block(256);
    conj_kernel<<<grid, block>>>(x, W, out);
}

// round 3
// speedup vs baseline: 1.5604x; 1.0127x over previous
#include <cuda_runtime.h>

// ConjunctionLayer: out[b,j] = -1/(-1 + sum_k log(1 - (1-x[b,k]) * W[j,k]))
// B=4096, D=512, N=128, fp32.
//
// sum(log Z) == log(prod Z), Z in (0.5, 1]: FMUL product chains, one log2 per
// 64 k's. Packed f32x2 math (even k in lo lane, odd k in hi lane). Register
// tile RB=2 x RJ=4. cp.async double-buffered k-major smem staging.

#define Bdim 4096
#define Ddim 512
#define Ndim 128

#define TB   16          // b-rows per CTA -> 256 CTAs
#define KC   32          // k per staged chunk
#define NCH  (Ddim / KC) // 16 chunks
#define SROW 36          // smem row stride in words (144B: 16B-aligned, stagger)
#define XW   (TB * SROW)        // 576 words
#define WW   (Ndim * SROW)      // 4608 words
#define BUFW (XW + WW)          // 5184 words per buffer

typedef unsigned long long ull;

__device__ __forceinline__ ull fma2(ull a, ull b, ull c) {
    ull d; asm("fma.rn.f32x2 %0, %1, %2, %3;" : "=l"(d) : "l"(a), "l"(b), "l"(c));
    return d;
}
__device__ __forceinline__ ull mul2(ull a, ull b) {
    ull d; asm("mul.rn.f32x2 %0, %1, %2;" : "=l"(d) : "l"(a), "l"(b));
    return d;
}
__device__ __forceinline__ ull add2(ull a, ull b) {
    ull d; asm("add.rn.f32x2 %0, %1, %2;" : "=l"(d) : "l"(a), "l"(b));
    return d;
}
__device__ __forceinline__ void unpack2(ull v, float& lo, float& hi) {
    asm("mov.b64 {%0, %1}, %2;" : "=f"(lo), "=f"(hi) : "l"(v));
}
__device__ __forceinline__ void cp16(unsigned smem_dst, const void* gsrc) {
    asm volatile("cp.async.cg.shared.global [%0], [%1], 16;\n"
                 :: "r"(smem_dst), "l"(gsrc));
}

__global__ __launch_bounds__(256, 2)
void conj_kernel(const float* __restrict__ x,
                 const float* __restrict__ W,
                 float* __restrict__ out) {
    __shared__ float smem[2 * BUFW];   // [buf][ sx(16x36) | sw(128x36) ]

    const int tid   = threadIdx.x;
    const int b_blk = blockIdx.x * TB;
    const int tj    = tid >> 3;        // 0..31 -> j group
    const int tb    = tid & 7;         // 0..7  -> b rows tb, tb+8
    const int j0    = tj * 4;

    const ull ONE2  = 0x3F8000003F800000ull;   // {1.0f, 1.0f}
    const ull NONE2 = 0xBF800000BF800000ull;   // {-1.0f, -1.0f}

    ull   prod[2][4];
    float lsum[2][4];
#pragma unroll
    for (int r = 0; r < 2; r++)
#pragma unroll
        for (int c = 0; c < 4; c++) { prod[r][c] = ONE2; lsum[r][c] = 0.0f; }

    const unsigned sbase = (unsigned)__cvta_generic_to_shared(smem);

    // staging maps (float4 granularity; KC=32 -> 8 float4 per row)
    // sw: 1024 f4/chunk, 4 per thread; sx: 128 f4/chunk, threads 0..127
    int wrow[4], wc4[4];
#pragma unroll
    for (int t = 0; t < 4; t++) {
        int idx = tid + t * 256;
        wrow[t] = idx >> 3;
        wc4[t]  = idx & 7;
    }
    const int xrow = tid >> 3;     // valid when tid < 128
    const int xc4  = tid & 7;

#define STAGE(CH, P)                                                          \
    do {                                                                      \
        int k0 = (CH) * KC;                                                   \
        unsigned bofs = sbase + (P) * (BUFW * 4);                             \
        _Pragma("unroll")                                                     \
        for (int t = 0; t < 4; t++)                                           \
            cp16(bofs + (XW + wrow[t] * SROW + wc4[t] * 4) * 4,               \
                 &W[wrow[t] * Ddim + k0 + wc4[t] * 4]);                       \
        if (tid < 128)                                                        \
            cp16(bofs + (xrow * SROW + xc4 * 4) * 4,                          \
                 &x[(b_blk + xrow) * Ddim + k0 + xc4 * 4]);                   \
        asm volatile("cp.async.commit_group;");                               \
    } while (0)

    STAGE(0, 0);

    for (int ch = 0; ch < NCH; ch++) {
        const int p = ch & 1;
        asm volatile("cp.async.wait_group 0;");
        __syncthreads();                 // buf p full; buf p^1 fully consumed
        if (ch + 1 < NCH) STAGE(ch + 1, p ^ 1);

        const float* bx = &smem[p * BUFW];
        const float* bw = &smem[p * BUFW + XW];

#pragma unroll
        for (int kk = 0; kk < KC; kk += 4) {
            ulonglong2 av0 = *(const ulonglong2*)&bx[tb * SROW + kk];
            ulonglong2 av1 = *(const ulonglong2*)&bx[(tb + 8) * SROW + kk];
            ull a0x = add2(av0.x, NONE2), a0y = add2(av0.y, NONE2);
            ull a1x = add2(av1.x, NONE2), a1y = add2(av1.y, NONE2);
#pragma unroll
            for (int c = 0; c < 4; c++) {
                ulonglong2 wv = *(const ulonglong2*)&bw[(j0 + c) * SROW + kk];
                prod[0][c] = mul2(prod[0][c], fma2(a0x, wv.x, ONE2));
                prod[0][c] = mul2(prod[0][c], fma2(a0y, wv.y, ONE2));
                prod[1][c] = mul2(prod[1][c], fma2(a1x, wv.x, ONE2));
                prod[1][c] = mul2(prod[1][c], fma2(a1y, wv.y, ONE2));
            }
        }

        if (ch & 1) {  // flush every 64 k's (min product 0.5^64, still normal)
#pragma unroll
            for (int r = 0; r < 2; r++)
#pragma unroll
                for (int c = 0; c < 4; c++) {
                    float lo, hi;
                    unpack2(prod[r][c], lo, hi);
                    lsum[r][c] += __log2f(lo * hi);
                    prod[r][c] = ONE2;
                }
        }
        // next iteration's __syncthreads protects buf p before restaging
    }

    // epilogue: y = -1 / (-1 + ln2 * sum_log2)
    const float LN2 = 0.6931471805599453f;
#pragma unroll
    for (int r = 0; r < 2; r++) {
        int b = b_blk + tb + r * 8;
        float v[4];
#pragma unroll
        for (int c = 0; c < 4; c++) {
            float s = lsum[r][c] * LN2;
            v[c] = __fdividef(-1.0f, s - 1.0f);
        }
        *(float4*)&out[b * Ndim + j0] = make_float4(v[0], v[1], v[2], v[3]);
    }
}

extern "C" void kernel_launch(void* const* d_in, const int* in_sizes, int n_in,
                              void* d_out, int out_size) {
    const float* x = (const float*)d_in[0];   // (4096, 512)
    const float* W = (const float*)d_in[1];   // (128, 512)
    float* out = (float*)d_out;               // (4096, 128)
    (void)in_sizes; (void)n_in; (void)out_size;

    dim3 grid(Bdim / TB);   // 256 CTAs
    dim3 block(256);
    conj_kernel<<<grid, block>>>(x, W, out);
}